// round 4
// baseline (speedup 1.0000x reference)
#include <cuda_runtime.h>
#include <cstdint>

#define Nn 4096
#define DI 512
#define DO 128
#define NH 4
#define BM 128
#define BK 32
#define BSTR 36          // padded row stride for pair-permuted tiles
#define WSTR 132         // W tile row stride [k][n]

// ---------------- device scratch ----------------
__device__ float g_h[Nn * DO];     // h fp32 row-major (for k_node)
__device__ float g_hT[DO * Nn];    // h tf32-rounded, transposed [d][node]
__device__ float g_el[NH * Nn], g_p[NH * Nn], g_p2[NH * Nn];
__device__ float g_er[NH * Nn], g_q[NH * Nn], g_q2[NH * Nn];

// ---------------- helpers ----------------
__device__ __forceinline__ uint32_t cvt_tf32(float x) {
    uint32_t r;
    asm("cvt.rna.tf32.f32 %0, %1;" : "=r"(r) : "f"(x));
    return r;
}
__device__ __forceinline__ void mma_tf32(float& c0, float& c1, float& c2, float& c3,
                                         uint32_t a0, uint32_t a1, uint32_t a2, uint32_t a3,
                                         uint32_t b0, uint32_t b1) {
    asm volatile("mma.sync.aligned.m16n8k8.row.col.f32.tf32.tf32.f32 "
                 "{%0,%1,%2,%3}, {%4,%5,%6,%7}, {%8,%9}, {%0,%1,%2,%3};"
                 : "+f"(c0), "+f"(c1), "+f"(c2), "+f"(c3)
                 : "r"(a0), "r"(a1), "r"(a2), "r"(a3), "r"(b0), "r"(b1));
}
__device__ __forceinline__ void lds64(uint32_t& x, uint32_t& y, const float* p) {
    asm volatile("ld.shared.v2.b32 {%0,%1}, [%2];" : "=r"(x), "=r"(y) : "l"(__cvta_generic_to_shared(p)));
}
__device__ __forceinline__ void sts64(float* p, uint32_t x, uint32_t y) {
    asm volatile("st.shared.v2.b32 [%0], {%1,%2};" :: "l"(__cvta_generic_to_shared(p)), "r"(x), "r"(y));
}
// pair-permutation: logical col j stored so (j, j+4) are adjacent (one lds64)
__device__ __forceinline__ int posk(int j) {
    return (j & 24) + ((j & 3) << 1) + ((j >> 2) & 1);
}

// ======================================================================
// Kernel 1: h = x @ W via mma.sync tf32, both operands staged in smem.
// 128 CTAs x 32 rows, 256 thr = 8 warps (2 M x 4 N), warp tile 16x32.
// K loop: 16 stages of BK=32. Writes g_h (fp32) + g_hT (tf32, transposed).
// ======================================================================
__global__ __launch_bounds__(256) void k_hgemm(const float* __restrict__ x,
                                               const float* __restrict__ W) {
    __shared__ float xs[32 * BSTR];    // pair-permuted x tile [row][k']
    __shared__ float Ws[32 * WSTR];    // W tile [k][n]

    int t = threadIdx.x, lane = t & 31, warp = t >> 5;
    int g = lane >> 2, ctg = lane & 3;
    int i0 = blockIdx.x * 32;
    int wm = warp >> 2, wn = warp & 3;
    int rmA = wm * 16 + g;             // A-frag rows (and +8)
    int n0 = wn * 32;

    float acc[4][4];
#pragma unroll
    for (int nt = 0; nt < 4; nt++)
#pragma unroll
        for (int c = 0; c < 4; c++) acc[nt][c] = 0.0f;

    // staging roles
    int xrow = t >> 3, xkq = (t & 7) * 4;               // x: 1 float4/thread
    for (int k0 = 0; k0 < DI; k0 += BK) {
        __syncthreads();
        {   // x tile
            float4 v = *reinterpret_cast<const float4*>(&x[(size_t)(i0 + xrow) * DI + k0 + xkq]);
            float* dst = &xs[xrow * BSTR];
            dst[posk(xkq + 0)] = __uint_as_float(cvt_tf32(v.x));
            dst[posk(xkq + 1)] = __uint_as_float(cvt_tf32(v.y));
            dst[posk(xkq + 2)] = __uint_as_float(cvt_tf32(v.z));
            dst[posk(xkq + 3)] = __uint_as_float(cvt_tf32(v.w));
            // W tile: 32k x 128n = 1024 float4s, flat
#pragma unroll
            for (int r = 0; r < 4; r++) {
                int f = t + 256 * r;
                int kr = f >> 5, nc = (f & 31) * 4;
                float4 w = *reinterpret_cast<const float4*>(&W[(size_t)(k0 + kr) * DO + nc]);
                float* wd = &Ws[kr * WSTR + nc];
                wd[0] = __uint_as_float(cvt_tf32(w.x));
                wd[1] = __uint_as_float(cvt_tf32(w.y));
                wd[2] = __uint_as_float(cvt_tf32(w.z));
                wd[3] = __uint_as_float(cvt_tf32(w.w));
            }
        }
        __syncthreads();
#pragma unroll
        for (int kk = 0; kk < 4; kk++) {
            uint32_t a0, a2, a1, a3;
            lds64(a0, a2, &xs[rmA * BSTR + kk * 8 + ctg * 2]);
            lds64(a1, a3, &xs[(rmA + 8) * BSTR + kk * 8 + ctg * 2]);
#pragma unroll
            for (int nt = 0; nt < 4; nt++) {
                int n = n0 + nt * 8 + g;
                uint32_t b0 = __float_as_uint(Ws[(kk * 8 + ctg) * WSTR + n]);
                uint32_t b1 = __float_as_uint(Ws[(kk * 8 + ctg + 4) * WSTR + n]);
                mma_tf32(acc[nt][0], acc[nt][1], acc[nt][2], acc[nt][3],
                         a0, a1, a2, a3, b0, b1);
            }
        }
    }

    // epilogue
    int rA = i0 + rmA, rB = rA + 8;
#pragma unroll
    for (int nt = 0; nt < 4; nt++) {
        int col = n0 + nt * 8 + ctg * 2;
        *reinterpret_cast<float2*>(&g_h[(size_t)rA * DO + col]) = make_float2(acc[nt][0], acc[nt][1]);
        *reinterpret_cast<float2*>(&g_h[(size_t)rB * DO + col]) = make_float2(acc[nt][2], acc[nt][3]);
        g_hT[(size_t)col * Nn + rA]       = __uint_as_float(cvt_tf32(acc[nt][0]));
        g_hT[(size_t)(col + 1) * Nn + rA] = __uint_as_float(cvt_tf32(acc[nt][1]));
        g_hT[(size_t)col * Nn + rB]       = __uint_as_float(cvt_tf32(acc[nt][2]));
        g_hT[(size_t)(col + 1) * Nn + rB] = __uint_as_float(cvt_tf32(acc[nt][3]));
    }
}

// ======================================================================
// Kernel 2: per-node projections + factorized exps.
// ======================================================================
__global__ __launch_bounds__(256) void k_node(const float* __restrict__ al,
                                              const float* __restrict__ ar) {
    int warp = threadIdx.x >> 5, lane = threadIdx.x & 31;
    int node = blockIdx.x * 8 + warp;
    float h0 = g_h[node * DO + lane];
    float h1 = g_h[node * DO + lane + 32];
    float h2 = g_h[node * DO + lane + 64];
    float h3 = g_h[node * DO + lane + 96];
#pragma unroll
    for (int hd = 0; hd < NH; hd++) {
        const float* wl = al + hd * DO;
        const float* wr = ar + hd * DO;
        float sl = h0 * wl[lane] + h1 * wl[lane + 32] + h2 * wl[lane + 64] + h3 * wl[lane + 96];
        float sr = h0 * wr[lane] + h1 * wr[lane + 32] + h2 * wr[lane + 64] + h3 * wr[lane + 96];
#pragma unroll
        for (int off = 16; off; off >>= 1) {
            sl += __shfl_xor_sync(0xffffffffu, sl, off);
            sr += __shfl_xor_sync(0xffffffffu, sr, off);
        }
        if (lane == 0) {
            int idx = hd * Nn + node;
            g_el[idx] = sl;
            g_p[idx]  = expf(sl);
            g_p2[idx] = expf(0.2f * sl);
            g_er[idx] = sr;
            g_q[idx]  = expf(sr);
            g_q2[idx] = expf(0.2f * sr);
        }
    }
}

// ======================================================================
// Kernel 3: fused masked-attention GEMM, double-buffered, 1 barrier/stage.
// Grid (NH, 32), 512 thr = 16 warps (4M x 4N). Per stage: produce tf32
// weight tile + h tile into buf s (from regs prefetched last stage), sync,
// prefetch stage it+1, then 32 mma on buf s (overlaps with other warps'
// prefetch + next produce never touches buf s).
// ======================================================================
__global__ __launch_bounds__(512, 1) void k_fused(const float* __restrict__ adj,
                                                  const float* __restrict__ bias,
                                                  float* __restrict__ out) {
    extern __shared__ float dsm[];
    // layout: ws[2][128*36] then hs[2][128*36]
    float* wsb[2] = { dsm,              dsm + BM * BSTR };
    float* hsb[2] = { dsm + 2 * BM * BSTR, dsm + 3 * BM * BSTR };
    __shared__ float rowsum_s[BM];

    int t = threadIdx.x, lane = t & 31, warp = t >> 5;
    int g = lane >> 2, ctg = lane & 3;
    int head = blockIdx.x;
    int i0   = blockIdx.y * BM;
    int rm   = (warp >> 2) * 32;
    int n0   = (warp & 3) * 32;

    // i-side per-row constants (rows warp + 16*i)
    float eli[8], pi[8], p2i[8], rsum[8];
#pragma unroll
    for (int i = 0; i < 8; i++) {
        int idx = head * Nn + i0 + warp + 16 * i;
        eli[i] = g_el[idx]; pi[i] = g_p[idx]; p2i[i] = g_p2[idx];
        rsum[i] = 0.0f;
    }
    const float* adj_base = adj + (size_t)(i0 + warp) * Nn + lane;
    const float* er_base  = g_er + head * Nn + lane;
    const float* q_base   = g_q  + head * Nn + lane;
    const float* q2_base  = g_q2 + head * Nn + lane;
    int wpos = posk(lane);
    int hn = t >> 2, hkq = (t & 3) * 8;
    const float* hT_base = g_hT + (size_t)hn * Nn + hkq;

    float acc[2][4][4];
#pragma unroll
    for (int mt = 0; mt < 2; mt++)
#pragma unroll
        for (int nt = 0; nt < 4; nt++)
#pragma unroll
            for (int c = 0; c < 4; c++) acc[mt][nt][c] = 0.0f;

    // --- prologue prefetch (stage 0) ---
    float areg[8];
    float4 hr0, hr1;
    float erj, qj, q2j;
#pragma unroll
    for (int i = 0; i < 8; i++) areg[i] = adj_base[(size_t)(16 * i) * Nn];
    hr0 = *reinterpret_cast<const float4*>(hT_base);
    hr1 = *reinterpret_cast<const float4*>(hT_base + 4);
    erj = er_base[0]; qj = q_base[0]; q2j = q2_base[0];

    const int NIT = Nn / BK;
    for (int it = 0; it < NIT; ++it) {
        int s = it & 1;
        float* ws = wsb[s];
        float* hs = hsb[s];

        // ---- produce buf s from prefetched regs ----
        {
            float pq[8], pq2[8];
#pragma unroll
            for (int i = 0; i < 8; i++) { pq[i] = pi[i] * qj; pq2[i] = p2i[i] * q2j; }
#pragma unroll
            for (int i = 0; i < 8; i++) {
                float sv = eli[i] + erj;
                float w = areg[i] * ((sv >= 0.0f) ? pq[i] : pq2[i]);
                float wf = __uint_as_float(cvt_tf32(w));
                rsum[i] += wf;
                ws[(warp + 16 * i) * BSTR + wpos] = wf;
            }
            float* hd = &hs[hn * BSTR + hkq];
            sts64(hd + 0, __float_as_uint(hr0.x), __float_as_uint(hr1.x));
            sts64(hd + 2, __float_as_uint(hr0.y), __float_as_uint(hr1.y));
            sts64(hd + 4, __float_as_uint(hr0.z), __float_as_uint(hr1.z));
            sts64(hd + 6, __float_as_uint(hr0.w), __float_as_uint(hr1.w));
        }
        __syncthreads();

        // ---- prefetch stage it+1 (overlaps the mma phase below) ----
        {
            int nk0 = (it + 1 < NIT) ? (it + 1) * BK : 0;
#pragma unroll
            for (int i = 0; i < 8; i++) areg[i] = adj_base[(size_t)(16 * i) * Nn + nk0];
            hr0 = *reinterpret_cast<const float4*>(hT_base + nk0);
            hr1 = *reinterpret_cast<const float4*>(hT_base + nk0 + 4);
            erj = er_base[nk0]; qj = q_base[nk0]; q2j = q2_base[nk0];
        }

        // ---- mma phase on buf s ----
#pragma unroll
        for (int kk = 0; kk < 4; kk++) {
            uint32_t b0[4], b1[4];
#pragma unroll
            for (int nt = 0; nt < 4; nt++)
                lds64(b0[nt], b1[nt], &hs[(n0 + nt * 8 + g) * BSTR + kk * 8 + ctg * 2]);
#pragma unroll
            for (int mt = 0; mt < 2; mt++) {
                uint32_t a0, a2, a1, a3;
                lds64(a0, a2, &ws[(rm + mt * 16 + g) * BSTR + kk * 8 + ctg * 2]);
                lds64(a1, a3, &ws[(rm + mt * 16 + 8 + g) * BSTR + kk * 8 + ctg * 2]);
#pragma unroll
                for (int nt = 0; nt < 4; nt++)
                    mma_tf32(acc[mt][nt][0], acc[mt][nt][1], acc[mt][nt][2], acc[mt][nt][3],
                             a0, a1, a2, a3, b0[nt], b1[nt]);
            }
        }
        // no second barrier: next produce targets buf s^1
    }

    // ---- rowsum reduce across lanes ----
#pragma unroll
    for (int i = 0; i < 8; i++) {
        float v = rsum[i];
#pragma unroll
        for (int off = 16; off; off >>= 1) v += __shfl_xor_sync(0xffffffffu, v, off);
        if (lane == 0) rowsum_s[warp + 16 * i] = v;
    }
    __syncthreads();

    // ---- epilogue: normalize + bias + store ----
#pragma unroll
    for (int mt = 0; mt < 2; mt++) {
        int lrA = rm + mt * 16 + g;
        int lrB = lrA + 8;
        float invA = 1.0f / fmaxf(rowsum_s[lrA], 1e-12f);
        float invB = 1.0f / fmaxf(rowsum_s[lrB], 1e-12f);
#pragma unroll
        for (int nt = 0; nt < 4; nt++) {
            int bcol = n0 + nt * 8 + ctg * 2;
            float2 bv = *reinterpret_cast<const float2*>(&bias[bcol]);
            float* opA = out + (size_t)(i0 + lrA) * (NH * DO) + head * DO + bcol;
            float* opB = out + (size_t)(i0 + lrB) * (NH * DO) + head * DO + bcol;
            *reinterpret_cast<float2*>(opA) =
                make_float2(acc[mt][nt][0] * invA + bv.x, acc[mt][nt][1] * invA + bv.y);
            *reinterpret_cast<float2*>(opB) =
                make_float2(acc[mt][nt][2] * invB + bv.x, acc[mt][nt][3] * invB + bv.y);
        }
    }
}

// ======================================================================
extern "C" void kernel_launch(void* const* d_in, const int* in_sizes, int n_in,
                              void* d_out, int out_size) {
    const float* adj = (const float*)d_in[0];
    const float* x   = (const float*)d_in[1];
    const float* W   = (const float*)d_in[2];
    const float* al  = (const float*)d_in[3];
    const float* ar  = (const float*)d_in[4];
    const float* b   = (const float*)d_in[5];
    float* out = (float*)d_out;

    const int dyn = 4 * BM * BSTR * sizeof(float);   // 73728 B
    cudaFuncSetAttribute(k_fused, cudaFuncAttributeMaxDynamicSharedMemorySize, dyn);

    k_hgemm<<<Nn / 32, 256>>>(x, W);
    k_node<<<Nn / 8, 256>>>(al, ar);
    k_fused<<<dim3(NH, Nn / BM), 512, dyn>>>(adj, b, out);
}